// round 6
// baseline (speedup 1.0000x reference)
#include <cuda_runtime.h>
#include <cuda_bf16.h>
#include <cstdint>

#define H_   128
#define B_   64
#define T_   10
#define N_   64
#define D_   4
#define E_   4032
#define BE_  258048
#define BN_  4096
#define EPS_ 1e-5f
#define LDK_  136          // padded k stride (bf16 elems)
#define LDKB_ 272          // bytes
// smem byte offsets for MMA tiles
#define A_HI 0
#define A_LO 34816
#define B_HI 69632
#define B_LO 104448
#define SM_MMA 139264

// ---------------- device scratch ----------------
__device__ __align__(16) float g_t1[BN_ * H_];
__device__ __align__(16) float g_P[BN_ * H_];
__device__ __align__(16) float g_Q[BN_ * H_];
__device__ __align__(16) float g_skip[BE_ * H_];
__device__ __align__(16) float g_h4[BE_ * H_];
__device__ __align__(16) float g_agg[BN_ * H_];
__device__ __align__(16) float g_t3[BN_ * H_];
__device__ __align__(16) float g_R[BN_ * H_];
__device__ __align__(16) float g_S[BN_ * H_];
__device__ __align__(16) float g_psum[BN_ * H_];
__device__ __align__(16) float g_pss[BN_ * H_];
__device__ __align__(16) float g_ab[8][H_];
__device__ __align__(16) float g_bias4[H_];
__device__ __align__(16) float g_fw[H_ * 2];
__device__ __align__(16) float g_fb[2];
// split bf16 weight images, [n][k] n-major, ld=LDK_
__device__ __align__(16) unsigned short g_w2hi[128 * LDK_];
__device__ __align__(16) unsigned short g_w2lo[128 * LDK_];
__device__ __align__(16) unsigned short g_w4hi[128 * LDK_];
__device__ __align__(16) unsigned short g_w4lo[128 * LDK_];
__device__ __align__(16) unsigned short g_wchi[128 * LDK_];
__device__ __align__(16) unsigned short g_wclo[128 * LDK_];

// ---------------- helpers ----------------
__device__ __forceinline__ float eluf(float x) { return x > 0.f ? x : (__expf(x) - 1.f); }

__device__ __forceinline__ void decode_edge(int gr, int& b, int& s, int& r) {
    b = gr / E_;
    int e = gr - b * E_;
    s = e / 63;
    int jj = e - s * 63;
    r = jj + (jj >= s ? 1 : 0);
}
__device__ __forceinline__ uint32_t smem_u32(const void* p) {
    uint32_t a;
    asm("{ .reg .u64 t; cvta.to.shared.u64 t, %1; cvt.u32.u64 %0, t; }" : "=r"(a) : "l"(p));
    return a;
}
__device__ __forceinline__ void split2(float x, float y, uint32_t& hi, uint32_t& lo) {
    __nv_bfloat162 h2 = __float22bfloat162_rn(make_float2(x, y));
    float lx = x - __bfloat162float(h2.x);
    float ly = y - __bfloat162float(h2.y);
    __nv_bfloat162 l2 = __float22bfloat162_rn(make_float2(lx, ly));
    hi = *reinterpret_cast<uint32_t*>(&h2);
    lo = *reinterpret_cast<uint32_t*>(&l2);
}

#define LDMX4(r0, r1, r2, r3, addr) \
    asm volatile("ldmatrix.sync.aligned.m8n8.x4.shared.b16 {%0,%1,%2,%3}, [%4];" \
        : "=r"(r0), "=r"(r1), "=r"(r2), "=r"(r3) : "r"(addr))
#define MMA16816(d, a0, a1, a2, a3, b0, b1) \
    asm volatile("mma.sync.aligned.m16n8k16.row.col.f32.bf16.bf16.f32 " \
        "{%0,%1,%2,%3}, {%4,%5,%6,%7}, {%8,%9}, {%0,%1,%2,%3};" \
        : "+f"((d)[0]), "+f"((d)[1]), "+f"((d)[2]), "+f"((d)[3]) \
        : "r"(a0), "r"(a1), "r"(a2), "r"(a3), "r"(b0), "r"(b1))

// one full K=128 product pass: acc += A(16x128) * B(128x128)^T
__device__ __forceinline__ void mma_pass(uint32_t aAddr, uint32_t bAddr, float acc[16][4]) {
#pragma unroll
    for (int ks = 0; ks < 8; ks++) {
        uint32_t a0, a1, a2, a3;
        LDMX4(a0, a1, a2, a3, aAddr + ks * 32);
#pragma unroll
        for (int t = 0; t < 8; t++) {
            uint32_t b0, b1, b2, b3;
            LDMX4(b0, b1, b2, b3, bAddr + t * (16 * LDKB_) + ks * 32);
            MMA16816(acc[2 * t],     a0, a1, a2, a3, b0, b1);
            MMA16816(acc[2 * t + 1], a0, a1, a2, a3, b2, b3);
        }
    }
}
__device__ __forceinline__ void copy_b(char* smc, const unsigned short* hi,
                                       const unsigned short* lo, int tid) {
    uint4* dh = (uint4*)(smc + B_HI);
    uint4* dl = (uint4*)(smc + B_LO);
    const uint4* sh = (const uint4*)hi;
    const uint4* sl = (const uint4*)lo;
    for (int i = tid; i < 2176; i += 256) { dh[i] = sh[i]; dl[i] = sl[i]; }
}

// ---------------- node-level kernels (unchanged) ----------------
__global__ void k_mlp1(const float* __restrict__ inp, const float* __restrict__ w1,
                       const float* __restrict__ b1, const float* __restrict__ w2,
                       const float* __restrict__ b2) {
    extern __shared__ float sm[];
    float* sW = sm;
    float* sX = sm + 16384;
    float* sH = sX + 32 * 40;
    int tid = threadIdx.x;
    int row0 = blockIdx.x * 32;
    for (int i = tid; i < 40 * 128; i += 128) sW[i] = w1[i];
    for (int i = tid; i < 32 * 40; i += 128) {
        int rr = i / 40, k = i - rr * 40;
        int row = row0 + rr, b = row >> 6, n = row & 63;
        int t = k >> 2, d = k & 3;
        sX[i] = inp[((b * T_ + t) * N_ + n) * D_ + d];
    }
    __syncthreads();
    int j = tid;
    float bj = b1[j];
    for (int rr = 0; rr < 32; rr++) {
        float acc = bj;
        for (int k = 0; k < 40; k++) acc += sX[rr * 40 + k] * sW[k * 128 + j];
        sH[rr * 128 + j] = eluf(acc);
    }
    __syncthreads();
    for (int i = tid; i < 16384; i += 128) sW[i] = w2[i];
    __syncthreads();
    float bj2 = b2[j], cs = 0.f, css = 0.f;
    for (int rr = 0; rr < 32; rr++) {
        float acc = bj2;
#pragma unroll 8
        for (int k = 0; k < 128; k++) acc += sH[rr * 128 + k] * sW[k * 128 + j];
        float v = eluf(acc);
        g_t1[(row0 + rr) * H_ + j] = v;
        cs += v; css += v * v;
    }
    g_psum[blockIdx.x * H_ + j] = cs;
    g_pss[blockIdx.x * H_ + j]  = css;
}

__global__ void k_mlp3(const float* __restrict__ w1, const float* __restrict__ b1,
                       const float* __restrict__ w2, const float* __restrict__ b2) {
    extern __shared__ float sm[];
    float* sW = sm;
    float* sX = sm + 16384;
    float* sH = sX + 32 * 128;
    int tid = threadIdx.x;
    int row0 = blockIdx.x * 32;
    for (int i = tid; i < 16384; i += 128) sW[i] = w1[i];
    for (int i = tid; i < 32 * 128; i += 128) {
        int rr = i >> 7, j = i & 127;
        sX[i] = g_agg[(row0 + rr) * H_ + j] * (g_ab[2][j] * (1.f / 63.f)) + g_ab[3][j];
    }
    __syncthreads();
    int j = tid;
    float bj = b1[j];
    for (int rr = 0; rr < 32; rr++) {
        float acc = bj;
#pragma unroll 8
        for (int k = 0; k < 128; k++) acc += sX[rr * 128 + k] * sW[k * 128 + j];
        sH[rr * 128 + j] = eluf(acc);
    }
    __syncthreads();
    for (int i = tid; i < 16384; i += 128) sW[i] = w2[i];
    __syncthreads();
    float bj2 = b2[j], cs = 0.f, css = 0.f;
    for (int rr = 0; rr < 32; rr++) {
        float acc = bj2;
#pragma unroll 8
        for (int k = 0; k < 128; k++) acc += sH[rr * 128 + k] * sW[k * 128 + j];
        float v = eluf(acc);
        g_t3[(row0 + rr) * H_ + j] = v;
        cs += v; css += v * v;
    }
    g_psum[blockIdx.x * H_ + j] = cs;
    g_pss[blockIdx.x * H_ + j]  = css;
}

__global__ void k_stats(int nblk, float invcnt, const float* __restrict__ g,
                        const float* __restrict__ beta, int sel) {
    __shared__ float s1[256], s2[256];
    int col = blockIdx.x, tid = threadIdx.x;
    float s = 0.f, ss = 0.f;
    for (int i = tid; i < nblk; i += 256) { s += g_psum[i * H_ + col]; ss += g_pss[i * H_ + col]; }
    s1[tid] = s; s2[tid] = ss;
    __syncthreads();
    for (int o = 128; o > 0; o >>= 1) {
        if (tid < o) { s1[tid] += s1[tid + o]; s2[tid] += s2[tid + o]; }
        __syncthreads();
    }
    if (tid == 0) {
        float mu = s1[0] * invcnt;
        float var = s2[0] * invcnt - mu * mu;
        float a = rsqrtf(var + EPS_) * g[col];
        g_ab[2 * sel][col] = a;
        g_ab[2 * sel + 1][col] = beta[col] - mu * a;
    }
}

__global__ void k_pair(const float* __restrict__ w, int sel) {
    extern __shared__ float sm[];
    float* sW = sm;
    float* sX = sm + 16384;
    const float* tin = sel ? g_t3 : g_t1;
    const float* a   = sel ? g_ab[4] : g_ab[0];
    const float* c   = sel ? g_ab[5] : g_ab[1];
    float* O1 = sel ? g_R : g_P;
    float* O2 = sel ? g_S : g_Q;
    int tid = threadIdx.x;
    int row0 = blockIdx.x * 32;
    for (int i = tid; i < 32 * 128; i += 128) {
        int rr = i >> 7, j = i & 127;
        sX[i] = tin[(row0 + rr) * H_ + j] * a[j] + c[j];
    }
    for (int i = tid; i < 16384; i += 128) sW[i] = w[i];
    __syncthreads();
    int j = tid;
    for (int rr = 0; rr < 32; rr++) {
        float acc = 0.f;
#pragma unroll 8
        for (int k = 0; k < 128; k++) acc += sX[rr * 128 + k] * sW[k * 128 + j];
        O1[(row0 + rr) * H_ + j] = acc;
    }
    __syncthreads();
    for (int i = tid; i < 16384; i += 128) sW[i] = w[16384 + i];
    __syncthreads();
    for (int rr = 0; rr < 32; rr++) {
        float acc = 0.f;
#pragma unroll 8
        for (int k = 0; k < 128; k++) acc += sX[rr * 128 + k] * sW[k * 128 + j];
        O2[(row0 + rr) * H_ + j] = acc;
    }
}

// ---------------- weight prep: split + transpose to [n][k] ----------------
__global__ void k_wprep(const float* __restrict__ w, int which) {
    int n = blockIdx.x, k = threadIdx.x;
    float v = w[k * H_ + n];
    unsigned short h = __bfloat16_as_ushort(__float2bfloat16_rn(v));
    float lo = v - __bfloat162float(__ushort_as_bfloat16(h));
    unsigned short l = __bfloat16_as_ushort(__float2bfloat16_rn(lo));
    int o = n * LDK_ + k;
    if (which == 0) { g_w2hi[o] = h; g_w2lo[o] = l; }
    else            { g_w4hi[o] = h; g_w4lo[o] = l; }
}
__global__ void k_wprepcp(const float* __restrict__ w41) {
    int n = blockIdx.x, k = threadIdx.x;
    float v = g_ab[2][k] * w41[(256 + k) * H_ + n];
    unsigned short h = __bfloat16_as_ushort(__float2bfloat16_rn(v));
    float lo = v - __bfloat162float(__ushort_as_bfloat16(h));
    unsigned short l = __bfloat16_as_ushort(__float2bfloat16_rn(lo));
    int o = n * LDK_ + k;
    g_wchi[o] = h; g_wclo[o] = l;
}
__global__ void k_bias4(const float* __restrict__ w41, const float* __restrict__ b41) {
    int j = threadIdx.x;
    float acc = b41[j];
    for (int k = 0; k < 128; k++) acc += g_ab[3][k] * w41[(256 + k) * H_ + j];
    g_bias4[j] = acc;
}

// ---------------- edge stage B via mma.sync ----------------
__global__ void __launch_bounds__(256, 1)
k_edge2m(const float* __restrict__ b1v, const float* __restrict__ b2v) {
    extern __shared__ char smc[];
    uint32_t sb = smem_u32(smc);
    int tid = threadIdx.x, wid = tid >> 5, lane = tid & 31;
    int row0 = blockIdx.x * 128;
    copy_b(smc, g_w2hi, g_w2lo, tid);
    {   // A = ELU(P[s]+Q[r]+b1), split into hi/lo tiles
        int m = tid & 127, k0 = (tid >> 7) * 64;
        int gr = row0 + m, b, s, r;
        decode_edge(gr, b, s, r);
        const float* pP = g_P + ((b << 6) + s) * H_;
        const float* pQ = g_Q + ((b << 6) + r) * H_;
        for (int kk = 0; kk < 64; kk += 8) {
            int k = k0 + kk;
            float4 p0 = *(const float4*)(pP + k), p1 = *(const float4*)(pP + k + 4);
            float4 q0 = *(const float4*)(pQ + k), q1 = *(const float4*)(pQ + k + 4);
            float4 c0 = *(const float4*)(b1v + k), c1 = *(const float4*)(b1v + k + 4);
            float v[8];
            v[0] = eluf(p0.x + q0.x + c0.x); v[1] = eluf(p0.y + q0.y + c0.y);
            v[2] = eluf(p0.z + q0.z + c0.z); v[3] = eluf(p0.w + q0.w + c0.w);
            v[4] = eluf(p1.x + q1.x + c1.x); v[5] = eluf(p1.y + q1.y + c1.y);
            v[6] = eluf(p1.z + q1.z + c1.z); v[7] = eluf(p1.w + q1.w + c1.w);
            uint32_t hi[4], lo[4];
#pragma unroll
            for (int i = 0; i < 4; i++) split2(v[2 * i], v[2 * i + 1], hi[i], lo[i]);
            *(uint4*)(smc + A_HI + m * LDKB_ + k * 2) = make_uint4(hi[0], hi[1], hi[2], hi[3]);
            *(uint4*)(smc + A_LO + m * LDKB_ + k * 2) = make_uint4(lo[0], lo[1], lo[2], lo[3]);
        }
    }
    __syncthreads();
    float acc[16][4];
#pragma unroll
    for (int i = 0; i < 16; i++) { acc[i][0] = acc[i][1] = acc[i][2] = acc[i][3] = 0.f; }
    uint32_t aOff = (wid * 16 + (lane & 15)) * LDKB_ + (lane >> 4) * 16;
    uint32_t bOff = (((lane >> 4) & 1) * 8 + (lane & 7)) * LDKB_ + ((lane >> 3) & 1) * 16;
    mma_pass(sb + A_HI + aOff, sb + B_HI + bOff, acc);
    mma_pass(sb + A_HI + aOff, sb + B_LO + bOff, acc);
    mma_pass(sb + A_LO + aOff, sb + B_HI + bOff, acc);

    int r = lane >> 2, cb = (lane & 3) * 2;
    int rowA = row0 + wid * 16 + r, rowB = rowA + 8;
#pragma unroll
    for (int nt = 0; nt < 16; nt++) {
        int c = nt * 8 + cb;
        float2 bv = *(const float2*)(b2v + c);
        *(float2*)(g_skip + rowA * H_ + c) =
            make_float2(eluf(acc[nt][0] + bv.x), eluf(acc[nt][1] + bv.y));
        *(float2*)(g_skip + rowB * H_ + c) =
            make_float2(eluf(acc[nt][2] + bv.x), eluf(acc[nt][3] + bv.y));
    }
}

// ---------------- edge stage D via mma.sync (both layers fused) ----------------
__global__ void __launch_bounds__(256, 1)
k_edge4m(const float* __restrict__ b42) {
    extern __shared__ char smc[];
    uint32_t sb = smem_u32(smc);
    int tid = threadIdx.x, wid = tid >> 5, lane = tid & 31;
    int row0 = blockIdx.x * 128;
    copy_b(smc, g_wchi, g_wclo, tid);
    {   // A = skip tile, split
        int m = tid & 127, k0 = (tid >> 7) * 64;
        const float* ps = g_skip + (row0 + m) * H_;
        for (int kk = 0; kk < 64; kk += 8) {
            int k = k0 + kk;
            float4 x0 = *(const float4*)(ps + k), x1 = *(const float4*)(ps + k + 4);
            uint32_t hi[4], lo[4];
            split2(x0.x, x0.y, hi[0], lo[0]); split2(x0.z, x0.w, hi[1], lo[1]);
            split2(x1.x, x1.y, hi[2], lo[2]); split2(x1.z, x1.w, hi[3], lo[3]);
            *(uint4*)(smc + A_HI + m * LDKB_ + k * 2) = make_uint4(hi[0], hi[1], hi[2], hi[3]);
            *(uint4*)(smc + A_LO + m * LDKB_ + k * 2) = make_uint4(lo[0], lo[1], lo[2], lo[3]);
        }
    }
    __syncthreads();
    float acc[16][4];
#pragma unroll
    for (int i = 0; i < 16; i++) { acc[i][0] = acc[i][1] = acc[i][2] = acc[i][3] = 0.f; }
    uint32_t aOff = (wid * 16 + (lane & 15)) * LDKB_ + (lane >> 4) * 16;
    uint32_t bOff = (((lane >> 4) & 1) * 8 + (lane & 7)) * LDKB_ + ((lane >> 3) & 1) * 16;
    mma_pass(sb + A_HI + aOff, sb + B_HI + bOff, acc);
    mma_pass(sb + A_HI + aOff, sb + B_LO + bOff, acc);
    mma_pass(sb + A_LO + aOff, sb + B_HI + bOff, acc);
    __syncthreads();   // all tile reads done before overwrite

    int r = lane >> 2, cb = (lane & 3) * 2;
    int rowA = row0 + wid * 16 + r, rowB = rowA + 8;
    int mA = wid * 16 + r, mB = mA + 8;
    {   // h3 = ELU(acc + R[s] + S[r] + bias4) -> back into A tiles (split)
        int bA, sA, rcA, bB, sB, rcB;
        decode_edge(rowA, bA, sA, rcA);
        decode_edge(rowB, bB, sB, rcB);
        const float* RA = g_R + ((bA << 6) + sA) * H_;
        const float* SA = g_S + ((bA << 6) + rcA) * H_;
        const float* RB = g_R + ((bB << 6) + sB) * H_;
        const float* SB = g_S + ((bB << 6) + rcB) * H_;
#pragma unroll
        for (int nt = 0; nt < 16; nt++) {
            int c = nt * 8 + cb;
            float2 b4 = *(const float2*)(g_bias4 + c);
            float2 ra = *(const float2*)(RA + c), sa = *(const float2*)(SA + c);
            float2 rb = *(const float2*)(RB + c), sbv = *(const float2*)(SB + c);
            float h0 = eluf(acc[nt][0] + ra.x + sa.x + b4.x);
            float h1 = eluf(acc[nt][1] + ra.y + sa.y + b4.y);
            float h2 = eluf(acc[nt][2] + rb.x + sbv.x + b4.x);
            float h3 = eluf(acc[nt][3] + rb.y + sbv.y + b4.y);
            uint32_t hw, lw;
            split2(h0, h1, hw, lw);
            *(uint32_t*)(smc + A_HI + mA * LDKB_ + c * 2) = hw;
            *(uint32_t*)(smc + A_LO + mA * LDKB_ + c * 2) = lw;
            split2(h2, h3, hw, lw);
            *(uint32_t*)(smc + A_HI + mB * LDKB_ + c * 2) = hw;
            *(uint32_t*)(smc + A_LO + mB * LDKB_ + c * 2) = lw;
        }
    }
    copy_b(smc, g_w4hi, g_w4lo, tid);
    __syncthreads();
#pragma unroll
    for (int i = 0; i < 16; i++) { acc[i][0] = acc[i][1] = acc[i][2] = acc[i][3] = 0.f; }
    mma_pass(sb + A_HI + aOff, sb + B_HI + bOff, acc);
    mma_pass(sb + A_HI + aOff, sb + B_LO + bOff, acc);
    mma_pass(sb + A_LO + aOff, sb + B_HI + bOff, acc);

    // epilogue 2: h4 = ELU(acc + b42) -> gmem, keep values for stats
#pragma unroll
    for (int nt = 0; nt < 16; nt++) {
        int c = nt * 8 + cb;
        float2 bv = *(const float2*)(b42 + c);
        acc[nt][0] = eluf(acc[nt][0] + bv.x); acc[nt][1] = eluf(acc[nt][1] + bv.y);
        acc[nt][2] = eluf(acc[nt][2] + bv.x); acc[nt][3] = eluf(acc[nt][3] + bv.y);
        *(float2*)(g_h4 + rowA * H_ + c) = make_float2(acc[nt][0], acc[nt][1]);
        *(float2*)(g_h4 + rowB * H_ + c) = make_float2(acc[nt][2], acc[nt][3]);
    }
    // deterministic BN4 stats: per-lane partials -> smem -> per-column reduce
    __syncthreads();
    float2* sSt = (float2*)smc;   // [8][32][16] float2 = 32 KB (A region reused)
#pragma unroll
    for (int nt = 0; nt < 16; nt++)
        sSt[(wid * 32 + lane) * 16 + nt] =
            make_float2(acc[nt][0] + acc[nt][2], acc[nt][1] + acc[nt][3]);
    __syncthreads();
    float ps = 0.f;
    if (tid < 128) {
        int q = (tid & 7) >> 1, nt = tid >> 3;
        for (int w8 = 0; w8 < 8; w8++)
            for (int rr = 0; rr < 8; rr++) {
                float2 v = sSt[(w8 * 32 + rr * 4 + q) * 16 + nt];
                ps += (tid & 1) ? v.y : v.x;
            }
    }
    __syncthreads();
#pragma unroll
    for (int nt = 0; nt < 16; nt++)
        sSt[(wid * 32 + lane) * 16 + nt] =
            make_float2(acc[nt][0] * acc[nt][0] + acc[nt][2] * acc[nt][2],
                        acc[nt][1] * acc[nt][1] + acc[nt][3] * acc[nt][3]);
    __syncthreads();
    if (tid < 128) {
        int q = (tid & 7) >> 1, nt = tid >> 3;
        float pss = 0.f;
        for (int w8 = 0; w8 < 8; w8++)
            for (int rr = 0; rr < 8; rr++) {
                float2 v = sSt[(w8 * 32 + rr * 4 + q) * 16 + nt];
                pss += (tid & 1) ? v.y : v.x;
            }
        g_psum[blockIdx.x * H_ + tid] = ps;
        g_pss[blockIdx.x * H_ + tid]  = pss;
    }
}

// edge2node segment-sum + BN2 stats partials
__global__ void k_agg() {
    int b = blockIdx.x >> 6, r = blockIdx.x & 63, j = threadIdx.x;
    const float* base = g_skip + (b * E_) * H_ + j;
    float s = 0.f, css = 0.f;
#pragma unroll 7
    for (int m = 0; m < 63; m++) {
        int i = m + (m >= r ? 1 : 0);
        int e = i * 63 + (m < r ? r - 1 : r);
        float v = base[e * H_];
        s += v; css += v * v;
    }
    g_agg[(b * N_ + r) * H_ + j] = s;
    g_psum[blockIdx.x * H_ + j] = s;
    g_pss[blockIdx.x * H_ + j]  = css;
}

__global__ void k_foldfc(const float* __restrict__ fcw, const float* __restrict__ fcb) {
    int j = threadIdx.x;
    g_fw[j * 2 + 0] = g_ab[6][j] * fcw[j * 2 + 0];
    g_fw[j * 2 + 1] = g_ab[6][j] * fcw[j * 2 + 1];
    if (j < 2) {
        float acc = fcb[j];
        for (int k = 0; k < 128; k++) acc += g_ab[7][k] * fcw[k * 2 + j];
        g_fb[j] = acc;
    }
}

__global__ void k_fc(float* __restrict__ out) {
    int w = (blockIdx.x * blockDim.x + threadIdx.x) >> 5;
    int lane = threadIdx.x & 31;
    if (w >= BE_) return;
    float4 h   = *(const float4*)(g_h4 + w * H_ + lane * 4);
    float4 fa  = *(const float4*)(g_fw + lane * 8);
    float4 fb4 = *(const float4*)(g_fw + lane * 8 + 4);
    float s0 = h.x * fa.x + h.y * fa.z + h.z * fb4.x + h.w * fb4.z;
    float s1 = h.x * fa.y + h.y * fa.w + h.z * fb4.y + h.w * fb4.w;
    for (int o = 16; o > 0; o >>= 1) {
        s0 += __shfl_xor_sync(0xffffffffu, s0, o);
        s1 += __shfl_xor_sync(0xffffffffu, s1, o);
    }
    if (lane == 0) *(float2*)(out + w * 2) = make_float2(s0 + g_fb[0], s1 + g_fb[1]);
}

// ---------------- host ----------------
extern "C" void kernel_launch(void* const* d_in, const int* in_sizes, int n_in,
                              void* d_out, int out_size) {
    const float* inp = (const float*)d_in[0];
    const float* w11 = (const float*)d_in[1];  const float* b11 = (const float*)d_in[2];
    const float* w12 = (const float*)d_in[3];  const float* b12 = (const float*)d_in[4];
    const float* g1  = (const float*)d_in[5];  const float* be1 = (const float*)d_in[6];
    const float* w21 = (const float*)d_in[7];  const float* b21 = (const float*)d_in[8];
    const float* w22 = (const float*)d_in[9];  const float* b22 = (const float*)d_in[10];
    const float* g2  = (const float*)d_in[11]; const float* be2 = (const float*)d_in[12];
    const float* w31 = (const float*)d_in[13]; const float* b31 = (const float*)d_in[14];
    const float* w32 = (const float*)d_in[15]; const float* b32 = (const float*)d_in[16];
    const float* g3  = (const float*)d_in[17]; const float* be3 = (const float*)d_in[18];
    const float* w41 = (const float*)d_in[19]; const float* b41 = (const float*)d_in[20];
    const float* w42 = (const float*)d_in[21]; const float* b42 = (const float*)d_in[22];
    const float* g4  = (const float*)d_in[23]; const float* be4 = (const float*)d_in[24];
    const float* fcw = (const float*)d_in[25]; const float* fcb = (const float*)d_in[26];
    float* out = (float*)d_out;

    const int SM_MLP1 = (16384 + 32 * 40 + 32 * 128) * 4;
    const int SM_MLP3 = (16384 + 32 * 128 + 32 * 128) * 4;
    const int SM_PAIR = (16384 + 32 * 128) * 4;

    cudaFuncSetAttribute(k_mlp1,   cudaFuncAttributeMaxDynamicSharedMemorySize, SM_MLP1);
    cudaFuncSetAttribute(k_mlp3,   cudaFuncAttributeMaxDynamicSharedMemorySize, SM_MLP3);
    cudaFuncSetAttribute(k_pair,   cudaFuncAttributeMaxDynamicSharedMemorySize, SM_PAIR);
    cudaFuncSetAttribute(k_edge2m, cudaFuncAttributeMaxDynamicSharedMemorySize, SM_MMA);
    cudaFuncSetAttribute(k_edge4m, cudaFuncAttributeMaxDynamicSharedMemorySize, SM_MMA);

    k_wprep<<<128, 128>>>(w22, 0);
    k_wprep<<<128, 128>>>(w42, 1);
    k_mlp1<<<128, 128, SM_MLP1>>>(inp, w11, b11, w12, b12);
    k_stats<<<128, 256>>>(128, 1.f / 4096.f, g1, be1, 0);
    k_pair<<<128, 128, SM_PAIR>>>(w21, 0);
    k_edge2m<<<2016, 256, SM_MMA>>>(b21, b22);
    k_agg<<<4096, 128>>>();
    k_stats<<<128, 256>>>(4096, 1.f / 258048.f, g2, be2, 1);
    k_mlp3<<<128, 128, SM_MLP3>>>(w31, b31, w32, b32);
    k_stats<<<128, 256>>>(128, 1.f / 4096.f, g3, be3, 2);
    k_pair<<<128, 128, SM_PAIR>>>(w41, 1);
    k_wprepcp<<<128, 128>>>(w41);
    k_bias4<<<1, 128>>>(w41, b41);
    k_edge4m<<<2016, 256, SM_MMA>>>(b42);
    k_stats<<<128, 256>>>(2016, 1.f / 258048.f, g4, be4, 3);
    k_foldfc<<<1, 128>>>(fcw, fcb);
    k_fc<<<BE_ * 32 / 256, 256>>>(out);
}

// round 8
// speedup vs baseline: 1.0226x; 1.0226x over previous
#include <cuda_runtime.h>

#define H_   128
#define B_   64
#define T_   10
#define N_   64
#define D_   4
#define E_   4032
#define BE_  258048
#define BN_  4096
#define EPS_ 1e-5f
#define XS_  68   // smem transposed-tile stride (floats)

// ---------------- device scratch ----------------
__device__ __align__(16) float g_t1[BN_ * H_];
__device__ __align__(16) float g_P[BN_ * H_];
__device__ __align__(16) float g_Q[BN_ * H_];
__device__ __align__(16) float g_skip[BE_ * H_];   // pre-BN mlp2 output
__device__ __align__(16) float g_h4[BE_ * H_];     // pre-BN mlp4 output
__device__ __align__(16) float g_agg[BN_ * H_];
__device__ __align__(16) float g_t3[BN_ * H_];
__device__ __align__(16) float g_R[BN_ * H_];
__device__ __align__(16) float g_S[BN_ * H_];
__device__ __align__(16) float g_psum[BN_ * H_];
__device__ __align__(16) float g_pss[BN_ * H_];
__device__ __align__(16) float g_ab[8][H_];        // a1,c1,a2,c2,a3,c3,a4,c4
__device__ __align__(16) float g_Wcp[H_ * H_];
__device__ __align__(16) float g_bias4[H_];
__device__ __align__(16) float g_fw[H_ * 2];
__device__ __align__(16) float g_fb[2];

// ---------------- helpers ----------------
__device__ __forceinline__ float eluf(float x) {
    return x > 0.f ? x : (__expf(x) - 1.f);
}

// packed dual fp32 FMA (Blackwell f32x2): c = a * (b,b) + c
__device__ __forceinline__ float2 ffma2s(float2 a, float bs, float2 c) {
    float2 b = make_float2(bs, bs);
    unsigned long long au = *reinterpret_cast<unsigned long long*>(&a);
    unsigned long long bu = *reinterpret_cast<unsigned long long*>(&b);
    unsigned long long cu = *reinterpret_cast<unsigned long long*>(&c);
    asm("fma.rn.f32x2 %0, %1, %2, %0;" : "+l"(cu) : "l"(au), "l"(bu));
    return *reinterpret_cast<float2*>(&cu);
}

__device__ __forceinline__ void decode_edge(int gr, int& b, int& s, int& r) {
    b = gr / E_;
    int e = gr - b * E_;
    s = e / 63;
    int jj = e - s * 63;
    r = jj + (jj >= s ? 1 : 0);
}

// one 32-k chunk; thread covers rows m0..m0+7 (4 float2 pairs) x cols c0..c0+3
__device__ __forceinline__ void gemm_chunk(const float* sWc, const float* sXTc,
                                           int m0, int c0, float2 acc[16]) {
#pragma unroll
    for (int kk = 0; kk < 32; kk++) {
        float4 w  = *(const float4*)(sWc + kk * 128 + c0);
        float4 ha = *(const float4*)(sXTc + kk * XS_ + m0);
        float4 hb = *(const float4*)(sXTc + kk * XS_ + m0 + 4);
        float2 h0 = make_float2(ha.x, ha.y), h1 = make_float2(ha.z, ha.w);
        float2 h2 = make_float2(hb.x, hb.y), h3 = make_float2(hb.z, hb.w);
        acc[0]  = ffma2s(h0, w.x, acc[0]);  acc[1]  = ffma2s(h0, w.y, acc[1]);
        acc[2]  = ffma2s(h0, w.z, acc[2]);  acc[3]  = ffma2s(h0, w.w, acc[3]);
        acc[4]  = ffma2s(h1, w.x, acc[4]);  acc[5]  = ffma2s(h1, w.y, acc[5]);
        acc[6]  = ffma2s(h1, w.z, acc[6]);  acc[7]  = ffma2s(h1, w.w, acc[7]);
        acc[8]  = ffma2s(h2, w.x, acc[8]);  acc[9]  = ffma2s(h2, w.y, acc[9]);
        acc[10] = ffma2s(h2, w.z, acc[10]); acc[11] = ffma2s(h2, w.w, acc[11]);
        acc[12] = ffma2s(h3, w.x, acc[12]); acc[13] = ffma2s(h3, w.y, acc[13]);
        acc[14] = ffma2s(h3, w.z, acc[14]); acc[15] = ffma2s(h3, w.w, acc[15]);
    }
}

__device__ __forceinline__ void load_chunk(float* dst, const float* __restrict__ W, int tid) {
    float4* d = (float4*)dst;
    const float4* s4 = (const float4*)W;
#pragma unroll
    for (int i = 0; i < 4; i++) d[tid + 256 * i] = s4[tid + 256 * i];
}

// full K=128 GEMM, double-buffered 32-k weight chunks (buffers at sW, sW+4096)
// precondition: sXT filled, no pending readers of sW buffers; ends with syncthreads.
__device__ __forceinline__ void gemm_streamW(float* sW, const float* sXT,
                                             const float* __restrict__ W,
                                             int tid, int m0, int c0, float2 acc[16]) {
    load_chunk(sW, W, tid);
    __syncthreads();
#pragma unroll
    for (int ch = 0; ch < 4; ch++) {
        if (ch < 3) load_chunk(sW + ((ch + 1) & 1) * 4096, W + (ch + 1) * 4096, tid);
        gemm_chunk(sW + (ch & 1) * 4096, sXT + ch * 32 * XS_, m0, c0, acc);
        __syncthreads();
    }
}

// ---------------- node-level kernels (4096 rows) ----------------
__global__ void k_mlp1(const float* __restrict__ inp, const float* __restrict__ w1,
                       const float* __restrict__ b1, const float* __restrict__ w2,
                       const float* __restrict__ b2) {
    extern __shared__ float sm[];
    float* sW = sm;
    float* sX = sm + 16384;
    float* sH = sX + 32 * 40;
    int tid = threadIdx.x;
    int row0 = blockIdx.x * 32;
    for (int i = tid; i < 40 * 128; i += 128) sW[i] = w1[i];
    for (int i = tid; i < 32 * 40; i += 128) {
        int rr = i / 40, k = i - rr * 40;
        int row = row0 + rr, b = row >> 6, n = row & 63;
        int t = k >> 2, d = k & 3;
        sX[i] = inp[((b * T_ + t) * N_ + n) * D_ + d];
    }
    __syncthreads();
    int j = tid;
    float bj = b1[j];
    for (int rr = 0; rr < 32; rr++) {
        float acc = bj;
        for (int k = 0; k < 40; k++) acc += sX[rr * 40 + k] * sW[k * 128 + j];
        sH[rr * 128 + j] = eluf(acc);
    }
    __syncthreads();
    for (int i = tid; i < 16384; i += 128) sW[i] = w2[i];
    __syncthreads();
    float bj2 = b2[j], cs = 0.f, css = 0.f;
    for (int rr = 0; rr < 32; rr++) {
        float acc = bj2;
#pragma unroll 8
        for (int k = 0; k < 128; k++) acc += sH[rr * 128 + k] * sW[k * 128 + j];
        float v = eluf(acc);
        g_t1[(row0 + rr) * H_ + j] = v;
        cs += v; css += v * v;
    }
    g_psum[blockIdx.x * H_ + j] = cs;
    g_pss[blockIdx.x * H_ + j]  = css;
}

__global__ void k_mlp3(const float* __restrict__ w1, const float* __restrict__ b1,
                       const float* __restrict__ w2, const float* __restrict__ b2) {
    extern __shared__ float sm[];
    float* sW = sm;
    float* sX = sm + 16384;
    float* sH = sX + 32 * 128;
    int tid = threadIdx.x;
    int row0 = blockIdx.x * 32;
    for (int i = tid; i < 16384; i += 128) sW[i] = w1[i];
    for (int i = tid; i < 32 * 128; i += 128) {
        int rr = i >> 7, j = i & 127;
        sX[i] = g_agg[(row0 + rr) * H_ + j] * (g_ab[2][j] * (1.f / 63.f)) + g_ab[3][j];
    }
    __syncthreads();
    int j = tid;
    float bj = b1[j];
    for (int rr = 0; rr < 32; rr++) {
        float acc = bj;
#pragma unroll 8
        for (int k = 0; k < 128; k++) acc += sX[rr * 128 + k] * sW[k * 128 + j];
        sH[rr * 128 + j] = eluf(acc);
    }
    __syncthreads();
    for (int i = tid; i < 16384; i += 128) sW[i] = w2[i];
    __syncthreads();
    float bj2 = b2[j], cs = 0.f, css = 0.f;
    for (int rr = 0; rr < 32; rr++) {
        float acc = bj2;
#pragma unroll 8
        for (int k = 0; k < 128; k++) acc += sH[rr * 128 + k] * sW[k * 128 + j];
        float v = eluf(acc);
        g_t3[(row0 + rr) * H_ + j] = v;
        cs += v; css += v * v;
    }
    g_psum[blockIdx.x * H_ + j] = cs;
    g_pss[blockIdx.x * H_ + j]  = css;
}

__global__ void k_stats(int nblk, float invcnt, const float* __restrict__ g,
                        const float* __restrict__ beta, int sel) {
    __shared__ float s1[256], s2[256];
    int col = blockIdx.x, tid = threadIdx.x;
    float s = 0.f, ss = 0.f;
    for (int i = tid; i < nblk; i += 256) { s += g_psum[i * H_ + col]; ss += g_pss[i * H_ + col]; }
    s1[tid] = s; s2[tid] = ss;
    __syncthreads();
    for (int o = 128; o > 0; o >>= 1) {
        if (tid < o) { s1[tid] += s1[tid + o]; s2[tid] += s2[tid + o]; }
        __syncthreads();
    }
    if (tid == 0) {
        float mu = s1[0] * invcnt;
        float var = s2[0] * invcnt - mu * mu;
        float a = rsqrtf(var + EPS_) * g[col];
        g_ab[2 * sel][col] = a;
        g_ab[2 * sel + 1][col] = beta[col] - mu * a;
    }
}

__global__ void k_pair(const float* __restrict__ w, int sel) {
    extern __shared__ float sm[];
    float* sW = sm;
    float* sX = sm + 16384;
    const float* tin = sel ? g_t3 : g_t1;
    const float* a   = sel ? g_ab[4] : g_ab[0];
    const float* c   = sel ? g_ab[5] : g_ab[1];
    float* O1 = sel ? g_R : g_P;
    float* O2 = sel ? g_S : g_Q;
    int tid = threadIdx.x;
    int row0 = blockIdx.x * 32;
    for (int i = tid; i < 32 * 128; i += 128) {
        int rr = i >> 7, j = i & 127;
        sX[i] = tin[(row0 + rr) * H_ + j] * a[j] + c[j];
    }
    for (int i = tid; i < 16384; i += 128) sW[i] = w[i];
    __syncthreads();
    int j = tid;
    for (int rr = 0; rr < 32; rr++) {
        float acc = 0.f;
#pragma unroll 8
        for (int k = 0; k < 128; k++) acc += sX[rr * 128 + k] * sW[k * 128 + j];
        O1[(row0 + rr) * H_ + j] = acc;
    }
    __syncthreads();
    for (int i = tid; i < 16384; i += 128) sW[i] = w[16384 + i];
    __syncthreads();
    for (int rr = 0; rr < 32; rr++) {
        float acc = 0.f;
#pragma unroll 8
        for (int k = 0; k < 128; k++) acc += sX[rr * 128 + k] * sW[k * 128 + j];
        O2[(row0 + rr) * H_ + j] = acc;
    }
}

// ---------------- edge stage B: skip_pre = ELU(ELU(P[s]+Q[r]+b1) @ W2 + b2) ----------------
// smem: sW double buffer 2x4096 f, then sXT 128*XS_ f
__global__ void __launch_bounds__(256, 3)
k_edge2(const float* __restrict__ W, const float* __restrict__ b1v,
        const float* __restrict__ b2v) {
    extern __shared__ float sm[];
    float* sW  = sm;
    float* sXT = sm + 8192;
    int tid = threadIdx.x;
    int row0 = blockIdx.x * 64;
    {
        int k = tid & 127, mh = tid >> 7;
        float bk = b1v[k];
        for (int m = mh; m < 64; m += 2) {
            int gr = row0 + m, b, s, r;
            decode_edge(gr, b, s, r);
            sXT[k * XS_ + m] = eluf(g_P[((b << 6) + s) * H_ + k] +
                                    g_Q[((b << 6) + r) * H_ + k] + bk);
        }
    }
    // 2-D warp tiling: warp = 32m x 32n, thread = 8m x 4n
    int m0 = ((tid >> 5) & 1) * 32 + ((tid & 31) >> 3) * 8;
    int c0 = (tid >> 6) * 32 + (tid & 7) * 4;
    float2 acc[16];
#pragma unroll
    for (int i = 0; i < 16; i++) acc[i] = make_float2(0.f, 0.f);
    gemm_streamW(sW, sXT, W, tid, m0, c0, acc);

    float4 bias = *(const float4*)(b2v + c0);
#pragma unroll
    for (int p = 0; p < 4; p++) {
        int rA = row0 + m0 + 2 * p;
        float4 va, vb;
        va.x = eluf(acc[p * 4 + 0].x + bias.x); va.y = eluf(acc[p * 4 + 1].x + bias.y);
        va.z = eluf(acc[p * 4 + 2].x + bias.z); va.w = eluf(acc[p * 4 + 3].x + bias.w);
        vb.x = eluf(acc[p * 4 + 0].y + bias.x); vb.y = eluf(acc[p * 4 + 1].y + bias.y);
        vb.z = eluf(acc[p * 4 + 2].y + bias.z); vb.w = eluf(acc[p * 4 + 3].y + bias.w);
        *(float4*)(g_skip + rA * H_ + c0) = va;
        *(float4*)(g_skip + (rA + 1) * H_ + c0) = vb;
    }
}

// ---------------- edge stage D (fused): two GEMMs, h3 stays on-chip ----------------
__global__ void __launch_bounds__(256, 3)
k_edge4(const float* __restrict__ W42, const float* __restrict__ b42) {
    extern __shared__ float sm[];
    float* sW  = sm;
    float* sXT = sm + 8192;
    int tid = threadIdx.x;
    int row0 = blockIdx.x * 64;
    {
        int k = tid & 127, mh = tid >> 7;
        for (int m = mh; m < 64; m += 2)
            sXT[k * XS_ + m] = g_skip[(row0 + m) * H_ + k];
    }
    int m0 = ((tid >> 5) & 1) * 32 + ((tid & 31) >> 3) * 8;
    int c0 = (tid >> 6) * 32 + (tid & 7) * 4;
    float2 acc[16];
#pragma unroll
    for (int i = 0; i < 16; i++) acc[i] = make_float2(0.f, 0.f);
    gemm_streamW(sW, sXT, g_Wcp, tid, m0, c0, acc);

    // epilogue 1: h3 = ELU(acc + R[s] + S[r] + bias4), write TRANSPOSED into sXT
    // (gemm_streamW ended with syncthreads -> all sXT reads done)
    {
        float4 b4v = *(const float4*)(g_bias4 + c0);
#pragma unroll
        for (int p = 0; p < 4; p++) {
            int rA = row0 + m0 + 2 * p, rB = rA + 1;
            int bA, sA, rcA, bB, sB, rcB;
            decode_edge(rA, bA, sA, rcA);
            decode_edge(rB, bB, sB, rcB);
            float4 RA = *(const float4*)(g_R + ((bA << 6) + sA) * H_ + c0);
            float4 SA = *(const float4*)(g_S + ((bA << 6) + rcA) * H_ + c0);
            float4 RB = *(const float4*)(g_R + ((bB << 6) + sB) * H_ + c0);
            float4 SB = *(const float4*)(g_S + ((bB << 6) + rcB) * H_ + c0);
            int mA = m0 + 2 * p, mB = mA + 1;
            sXT[(c0 + 0) * XS_ + mA] = eluf(acc[p * 4 + 0].x + RA.x + SA.x + b4v.x);
            sXT[(c0 + 1) * XS_ + mA] = eluf(acc[p * 4 + 1].x + RA.y + SA.y + b4v.y);
            sXT[(c0 + 2) * XS_ + mA] = eluf(acc[p * 4 + 2].x + RA.z + SA.z + b4v.z);
            sXT[(c0 + 3) * XS_ + mA] = eluf(acc[p * 4 + 3].x + RA.w + SA.w + b4v.w);
            sXT[(c0 + 0) * XS_ + mB] = eluf(acc[p * 4 + 0].y + RB.x + SB.x + b4v.x);
            sXT[(c0 + 1) * XS_ + mB] = eluf(acc[p * 4 + 1].y + RB.y + SB.y + b4v.y);
            sXT[(c0 + 2) * XS_ + mB] = eluf(acc[p * 4 + 2].y + RB.z + SB.z + b4v.z);
            sXT[(c0 + 3) * XS_ + mB] = eluf(acc[p * 4 + 3].y + RB.w + SB.w + b4v.w);
        }
    }
    __syncthreads();   // sXT writes visible before phase-2 reads
#pragma unroll
    for (int i = 0; i < 16; i++) acc[i] = make_float2(0.f, 0.f);
    gemm_streamW(sW, sXT, W42, tid, m0, c0, acc);

    // epilogue 2: h4 = ELU(acc + b42) -> gmem, + BN4 stats partials
    float4 bias = *(const float4*)(b42 + c0);
    float cs[4] = {0, 0, 0, 0}, css[4] = {0, 0, 0, 0};
#pragma unroll
    for (int p = 0; p < 4; p++) {
        int rA = row0 + m0 + 2 * p;
        float4 va, vb;
        va.x = eluf(acc[p * 4 + 0].x + bias.x); va.y = eluf(acc[p * 4 + 1].x + bias.y);
        va.z = eluf(acc[p * 4 + 2].x + bias.z); va.w = eluf(acc[p * 4 + 3].x + bias.w);
        vb.x = eluf(acc[p * 4 + 0].y + bias.x); vb.y = eluf(acc[p * 4 + 1].y + bias.y);
        vb.z = eluf(acc[p * 4 + 2].y + bias.z); vb.w = eluf(acc[p * 4 + 3].y + bias.w);
        *(float4*)(g_h4 + rA * H_ + c0) = va;
        *(float4*)(g_h4 + (rA + 1) * H_ + c0) = vb;
        cs[0] += va.x + vb.x; css[0] += va.x * va.x + vb.x * vb.x;
        cs[1] += va.y + vb.y; css[1] += va.y * va.y + vb.y * vb.y;
        cs[2] += va.z + vb.z; css[2] += va.z * va.z + vb.z * vb.z;
        cs[3] += va.w + vb.w; css[3] += va.w * va.w + vb.w * vb.w;
    }
    // deterministic column-stats reduction; sRed aliases the weight buffers
    float* sRed = sm;   // 8 slots x 128 cols
    int slot = ((tid >> 5) & 1) * 4 + ((tid & 31) >> 3);
    __syncthreads();
#pragma unroll
    for (int jj = 0; jj < 4; jj++) sRed[slot * 128 + c0 + jj] = cs[jj];
    __syncthreads();
    float ps = 0.f;
    if (tid < 128) for (int g8 = 0; g8 < 8; g8++) ps += sRed[g8 * 128 + tid];
    __syncthreads();
#pragma unroll
    for (int jj = 0; jj < 4; jj++) sRed[slot * 128 + c0 + jj] = css[jj];
    __syncthreads();
    if (tid < 128) {
        float pss = 0.f;
        for (int g8 = 0; g8 < 8; g8++) pss += sRed[g8 * 128 + tid];
        g_psum[blockIdx.x * H_ + tid] = ps;
        g_pss[blockIdx.x * H_ + tid]  = pss;
    }
}

// edge2node deterministic segment-sum + BN2 stats partials
__global__ void k_agg() {
    int b = blockIdx.x >> 6, r = blockIdx.x & 63, j = threadIdx.x;
    const float* base = g_skip + (b * E_) * H_ + j;
    float s = 0.f, css = 0.f;
#pragma unroll 7
    for (int m = 0; m < 63; m++) {
        int i = m + (m >= r ? 1 : 0);
        int e = i * 63 + (m < r ? r - 1 : r);
        float v = base[e * H_];
        s += v; css += v * v;
    }
    g_agg[(b * N_ + r) * H_ + j] = s;
    g_psum[blockIdx.x * H_ + j] = s;
    g_pss[blockIdx.x * H_ + j]  = css;
}

// fold BN2 into skip slice of mlp4_w1
__global__ void k_wcp(const float* __restrict__ w41) {
    int k = blockIdx.x, j = threadIdx.x;
    g_Wcp[k * H_ + j] = g_ab[2][k] * w41[(256 + k) * H_ + j];
}
__global__ void k_bias4(const float* __restrict__ w41, const float* __restrict__ b41) {
    int j = threadIdx.x;
    float acc = b41[j];
    for (int k = 0; k < 128; k++) acc += g_ab[3][k] * w41[(256 + k) * H_ + j];
    g_bias4[j] = acc;
}

// fold BN4 into fc
__global__ void k_foldfc(const float* __restrict__ fcw, const float* __restrict__ fcb) {
    int j = threadIdx.x;
    g_fw[j * 2 + 0] = g_ab[6][j] * fcw[j * 2 + 0];
    g_fw[j * 2 + 1] = g_ab[6][j] * fcw[j * 2 + 1];
    if (j < 2) {
        float acc = fcb[j];
        for (int k = 0; k < 128; k++) acc += g_ab[7][k] * fcw[k * 2 + j];
        g_fb[j] = acc;
    }
}

// final logits: warp per row
__global__ void k_fc(float* __restrict__ out) {
    int w = (blockIdx.x * blockDim.x + threadIdx.x) >> 5;
    int lane = threadIdx.x & 31;
    if (w >= BE_) return;
    float4 h   = *(const float4*)(g_h4 + w * H_ + lane * 4);
    float4 fa  = *(const float4*)(g_fw + lane * 8);
    float4 fb4 = *(const float4*)(g_fw + lane * 8 + 4);
    float s0 = h.x * fa.x + h.y * fa.z + h.z * fb4.x + h.w * fb4.z;
    float s1 = h.x * fa.y + h.y * fa.w + h.z * fb4.y + h.w * fb4.w;
    for (int o = 16; o > 0; o >>= 1) {
        s0 += __shfl_xor_sync(0xffffffffu, s0, o);
        s1 += __shfl_xor_sync(0xffffffffu, s1, o);
    }
    if (lane == 0) *(float2*)(out + w * 2) = make_float2(s0 + g_fb[0], s1 + g_fb[1]);
}

// ---------------- host ----------------
extern "C" void kernel_launch(void* const* d_in, const int* in_sizes, int n_in,
                              void* d_out, int out_size) {
    const float* inp = (const float*)d_in[0];
    const float* w11 = (const float*)d_in[1];  const float* b11 = (const float*)d_in[2];
    const float* w12 = (const float*)d_in[3];  const float* b12 = (const float*)d_in[4];
    const float* g1  = (const float*)d_in[5];  const float* be1 = (const float*)d_in[6];
    const float* w21 = (const float*)d_in[7];  const float* b21 = (const float*)d_in[8];
    const float* w22 = (const float*)d_in[9];  const float* b22 = (const float*)d_in[10];
    const float* g2  = (const float*)d_in[11]; const float* be2 = (const float*)d_in[12];
    const float* w31 = (const float*)d_in[13]; const float* b31 = (const float*)d_in[14];
    const float* w32 = (const float*)d_in[15]; const float* b32 = (const float*)d_in[16];
    const float* g3  = (const float*)d_in[17]; const float* be3 = (const float*)d_in[18];
    const float* w41 = (const float*)d_in[19]; const float* b41 = (const float*)d_in[20];
    const float* w42 = (const float*)d_in[21]; const float* b42 = (const float*)d_in[22];
    const float* g4  = (const float*)d_in[23]; const float* be4 = (const float*)d_in[24];
    const float* fcw = (const float*)d_in[25]; const float* fcb = (const float*)d_in[26];
    float* out = (float*)d_out;

    const int SM_MLP1 = (16384 + 32 * 40 + 32 * 128) * 4;
    const int SM_MLP3 = (16384 + 32 * 128 + 32 * 128) * 4;
    const int SM_PAIR = (16384 + 32 * 128) * 4;
    const int SM_EDGE = (8192 + XS_ * 128) * 4;   // 67584 B -> 3 blocks/SM

    cudaFuncSetAttribute(k_mlp1,  cudaFuncAttributeMaxDynamicSharedMemorySize, SM_MLP1);
    cudaFuncSetAttribute(k_mlp3,  cudaFuncAttributeMaxDynamicSharedMemorySize, SM_MLP3);
    cudaFuncSetAttribute(k_pair,  cudaFuncAttributeMaxDynamicSharedMemorySize, SM_PAIR);
    cudaFuncSetAttribute(k_edge2, cudaFuncAttributeMaxDynamicSharedMemorySize, SM_EDGE);
    cudaFuncSetAttribute(k_edge4, cudaFuncAttributeMaxDynamicSharedMemorySize, SM_EDGE);

    k_mlp1<<<128, 128, SM_MLP1>>>(inp, w11, b11, w12, b12);
    k_stats<<<128, 256>>>(128, 1.f / 4096.f, g1, be1, 0);
    k_pair<<<128, 128, SM_PAIR>>>(w21, 0);
    k_edge2<<<4032, 256, SM_EDGE>>>(w22, b21, b22);
    k_agg<<<4096, 128>>>();
    k_stats<<<128, 256>>>(4096, 1.f / 258048.f, g2, be2, 1);
    k_mlp3<<<128, 128, SM_MLP3>>>(w31, b31, w32, b32);
    k_stats<<<128, 256>>>(128, 1.f / 4096.f, g3, be3, 2);
    k_pair<<<128, 128, SM_PAIR>>>(w41, 1);
    k_wcp<<<128, 128>>>(w41);
    k_bias4<<<1, 128>>>(w41, b41);
    k_edge4<<<4032, 256, SM_EDGE>>>(w42, b42);
    k_stats<<<128, 256>>>(4032, 1.f / 258048.f, g4, be4, 3);
    k_foldfc<<<1, 128>>>(fcw, fcb);
    k_fc<<<BE_ * 32 / 256, 256>>>(out);
}